// round 13
// baseline (speedup 1.0000x reference)
#include <cuda_runtime.h>
#include <cstdint>

// out[b, 0:128]   = x[b, :]                       for b < B
// out[b, 128:256] = sum_{e: dst[e]==b} x[src[e]]
//
// Pipeline (2 graph nodes, PDL-overlapped):
//   K1 bin:  ELL binning (scalar, one edge/thread) + the bin-independent
//            first-half copy out[b,0:128]=x[b] folded into its latency-idle
//            issue slots (grid-stride float4 loop). All stores precede the
//            PDL trigger.
//   K2 main: PDL-dependent; R11-exact gather loop (untouchable — any store
//            BEFORE the loop destroys ptxas load batching, measured 3x).
//            Now writes ONLY the second half (copy moved to bin) -> ~50MB
//            less traffic. Trailing self-cleans replace all memsets.

#define NFEAT   128
#define ROW_OUT 256
#define MAX_E   640000
#define B_MAX   65536
#define SLOTS   32

__device__ int  g_cnt[B_MAX];
__device__ int  g_ell[B_MAX * SLOTS];
__device__ int2 g_ovf[MAX_E];
__device__ int  g_ovf_count;

__global__ void bin_kernel(const int* __restrict__ ei,
                           const float* __restrict__ x,
                           float* __restrict__ out,
                           int E, int B) {
    int i = blockIdx.x * blockDim.x + threadIdx.x;
    int nthreads = gridDim.x * blockDim.x;

    // Edge binning (one edge per thread).
    if (i < E) {
        int d = __ldg(ei + E + i);
        if ((unsigned)d < (unsigned)B) {
            int s = __ldg(ei + i);
            int k = atomicAdd(&g_cnt[d], 1);
            if (k < SLOTS) {
                g_ell[d * SLOTS + k] = s;
            } else {
                int p = atomicAdd(&g_ovf_count, 1);
                g_ovf[p] = make_int2(s, d);
            }
        }
    }

    // Bin-independent first-half copy: out[b, 0:128] = x[b, :].
    // Grid-stride over B*32 float4s; streaming work that fills the issue
    // slots this kernel otherwise wastes waiting on its atomic chains.
    int nq = B * (NFEAT / 4);
    for (int q = i; q < nq; q += nthreads) {
        int row = q >> 5;            // /32 quads per row
        int c4  = q & 31;
        float4 v = __ldg(reinterpret_cast<const float4*>(
                             x + (size_t)row * NFEAT) + c4);
        reinterpret_cast<float4*>(out + (size_t)row * ROW_OUT)[c4] = v;
    }

    // Allow the dependent main_kernel to begin; its
    // cudaGridDependencySynchronize orders against all stores above.
    cudaTriggerProgrammaticLaunchCompletion();
}

__global__ void main_kernel(const float* __restrict__ x,
                            float* __restrict__ out,
                            int B) {
    cudaGridDependencySynchronize();

    int warp = (blockIdx.x * blockDim.x + threadIdx.x) >> 5;
    int lane = threadIdx.x & 31;
    if (warp >= B) return;
    int b = warp;

    int c_raw = g_cnt[b];
    int c = c_raw < SLOTS ? c_raw : SLOTS;

    // Coalesced preload of this row's source list (one slot per lane).
    int src_l = (lane < c) ? g_ell[b * SLOTS + lane] : 0;

    float4 acc = make_float4(0.f, 0.f, 0.f, 0.f);
    for (int k = 0; k < c; k++) {
        int se = __shfl_sync(0xFFFFFFFFu, src_l, k);
        float4 v = __ldg(reinterpret_cast<const float4*>(
                             x + (size_t)se * NFEAT) + lane);
        acc.x += v.x; acc.y += v.y; acc.z += v.z; acc.w += v.w;
    }

    // Rare path: degree exceeded SLOTS -> extras live in the overflow list.
    if (c_raw > SLOTS) {
        int n = g_ovf_count;
        for (int e = 0; e < n; e++) {
            int2 ed = g_ovf[e];
            if (ed.y == b) {
                float4 v = __ldg(reinterpret_cast<const float4*>(
                                     x + (size_t)ed.x * NFEAT) + lane);
                acc.x += v.x; acc.y += v.y; acc.z += v.z; acc.w += v.w;
            }
        }
    }

    // Second half only (first half written by bin_kernel).
    float4* orow = reinterpret_cast<float4*>(out + (size_t)b * ROW_OUT);
    orow[(NFEAT / 4) + lane] = acc;

    // Trailing self-clean (measured benign): restores counters for the
    // next graph replay; no memset nodes needed.
    if (lane == 0) g_cnt[b] = 0;
    if (b == 0 && lane == 0) g_ovf_count = 0;
}

extern "C" void kernel_launch(void* const* d_in, const int* in_sizes, int n_in,
                              void* d_out, int out_size) {
    const float* x        = (const float*)d_in[0];
    const int*   edge_idx = (const int*)d_in[1];
    float*       out      = (float*)d_out;

    int B = out_size / ROW_OUT;          // 50000
    int E = in_sizes[1] / 2;             // 640000

    {   // K1: ELL binning + first-half copy
        int threads = 256;
        int blocks = (E + threads - 1) / threads;
        bin_kernel<<<blocks, threads>>>(edge_idx, x, out, E, B);
    }
    {   // K2: main gather-accumulate, PDL-overlapped with bin's tail
        int threads = 256;                          // 8 warps/block
        int blocks = (B + 7) / 8;

        cudaLaunchConfig_t cfg = {};
        cfg.gridDim  = dim3(blocks, 1, 1);
        cfg.blockDim = dim3(threads, 1, 1);
        cfg.dynamicSmemBytes = 0;
        cfg.stream = 0;
        cudaLaunchAttribute attrs[1];
        attrs[0].id = cudaLaunchAttributeProgrammaticStreamSerialization;
        attrs[0].val.programmaticStreamSerializationAllowed = 1;
        cfg.attrs = attrs;
        cfg.numAttrs = 1;
        cudaLaunchKernelEx(&cfg, main_kernel, x, out, B);
    }
}